// round 7
// baseline (speedup 1.0000x reference)
#include <cuda_runtime.h>

// GAT over 16384 independent 32-node cliques, fully fused: one CTA per graph.
// fp32x2 packed math + bank-exact tiles. Attention scores are folded into the
// GEMM epilogues (register dot + shfl reduce); the layer-3 tail is collapsed
// algebraically: out = (sum_j beta[j] h3[j] + b3) @ lw + lb, beta = mean_n alpha.

#define NCOL 32
#define HEADS 4
#define FH 128          // H * HID
#define FHP 132         // padded h row; consecutive rows conflict-free for f4
#define F3 24           // H * OUT
#define XINP 20
#define THREADS 128
#define NEG_SLOPE 0.2f

typedef unsigned long long u64;

__device__ float W3p_g[FH * 32];   // W3 padded: [f][head*8+d], zeros at d=6,7
__device__ float as3p_g[32];       // a_src3 padded [head*8+d]
__device__ float ad3p_g[32];       // a_dst3 padded

__device__ __forceinline__ float lrelu(float x) { return x > 0.f ? x : NEG_SLOPE * x; }

__device__ __forceinline__ u64 dup2(float x) {
    u64 r; asm("mov.b64 %0,{%1,%1};" : "=l"(r) : "f"(x)); return r;
}
__device__ __forceinline__ u64 pack2(float a, float b) {
    u64 r; asm("mov.b64 %0,{%1,%2};" : "=l"(r) : "f"(a), "f"(b)); return r;
}
__device__ __forceinline__ float2 unpack2(u64 v) {
    float2 r; asm("mov.b64 {%0,%1},%2;" : "=f"(r.x), "=f"(r.y) : "l"(v)); return r;
}
__device__ __forceinline__ void fma2(u64 &d, u64 a, u64 b) {
    asm("fma.rn.f32x2 %0,%1,%2,%0;" : "+l"(d) : "l"(a), "l"(b));
}
__device__ __forceinline__ void add2(u64 &d, u64 a) {
    asm("add.rn.f32x2 %0,%0,%1;" : "+l"(d) : "l"(a));
}
__device__ __forceinline__ u64 shfl_xor_u64(u64 v, int m) {
    unsigned lo, hi;
    asm("mov.b64 {%0,%1},%2;" : "=r"(lo), "=r"(hi) : "l"(v));
    lo = __shfl_xor_sync(0xffffffffu, lo, m);
    hi = __shfl_xor_sync(0xffffffffu, hi, m);
    u64 r; asm("mov.b64 %0,{%1,%2};" : "=l"(r) : "r"(lo), "r"(hi));
    return r;
}

__global__ void prep_kernel(const float* __restrict__ W3,
                            const float* __restrict__ as3,
                            const float* __restrict__ ad3) {
    int idx = blockIdx.x * blockDim.x + threadIdx.x;
    if (idx < FH * 32) {
        int f = idx >> 5, hp = idx & 31, d = hp & 7, h = hp >> 3;
        W3p_g[idx] = (d < 6) ? W3[f * F3 + h * 6 + d] : 0.f;
    } else if (idx < FH * 32 + 32) {
        int i = idx - FH * 32, h = i >> 3, d = i & 7;
        as3p_g[i] = (d < 6) ? as3[h * 6 + d] : 0.f;
    } else if (idx < FH * 32 + 64) {
        int i = idx - FH * 32 - 32, h = i >> 3, d = i & 7;
        ad3p_g[i] = (d < 6) ? ad3[h * 6 + d] : 0.f;
    }
}

// Attention phases 2+3 for D=32 (scores already in s_src/s_dst), in-place on h.
__device__ __forceinline__ void gat_attention32_post(
    float (*__restrict__ h)[FHP],
    const float* __restrict__ bias,
    const float* __restrict__ s_src, const float* __restrict__ s_dst,
    float (*__restrict__ alpha)[NCOL], int head, int lane)
{
    const int c0 = head * 32;
    __syncwarp();   // scores (STS by this warp) + h stores visible

    // phase 2: softmax for target = lane; store rotated, rinv-scaled alpha
    {
        const float sdst = s_dst[head * NCOL + lane];
        float e[NCOL];
        float m = -1e30f;
#pragma unroll
        for (int q = 0; q < 8; q++) {
            float4 sv = *(const float4*)&s_src[head * NCOL + 4 * q];
            e[4*q+0] = lrelu(sdst + sv.x);
            e[4*q+1] = lrelu(sdst + sv.y);
            e[4*q+2] = lrelu(sdst + sv.z);
            e[4*q+3] = lrelu(sdst + sv.w);
        }
#pragma unroll
        for (int j = 0; j < NCOL; j++) m = fmaxf(m, e[j]);
        float sum = 0.f;
#pragma unroll
        for (int j = 0; j < NCOL; j++) {
            e[j] = __expf(e[j] - m);
            sum += e[j];
        }
        const float rinv = 1.f / sum;
        const int rot = lane >> 2;
#pragma unroll
        for (int q = 0; q < 8; q++) {
            int col = ((q + rot) & 7) * 4;
            float4 v;
            v.x = e[4*q+0] * rinv;
            v.y = e[4*q+1] * rinv;
            v.z = e[4*q+2] * rinv;
            v.w = e[4*q+3] * rinv;
            *(float4*)&alpha[lane][col] = v;
        }
    }
    __syncwarp();

    // phase 3: out(32x32) = alpha @ h_head (channel-packed)
    const int ng = lane >> 2;
    const int cg = lane & 3;
    const int cb = c0 + 8 * cg;
    u64 acc2[4][4];
#pragma unroll
    for (int i = 0; i < 4; i++)
#pragma unroll
        for (int p = 0; p < 4; p++) acc2[i][p] = 0;

#pragma unroll
    for (int j0 = 0; j0 < NCOL; j0 += 4) {
        float4 av[4];
        const int colb = (((j0 >> 2) + ng) & 7) * 4;
#pragma unroll
        for (int i = 0; i < 4; i++)
            av[i] = *(const float4*)&alpha[4 * ng + i][colb];
#pragma unroll
        for (int jj = 0; jj < 4; jj++) {
            ulonglong2 h0 = *(const ulonglong2*)&h[j0 + jj][cb];
            ulonglong2 h1 = *(const ulonglong2*)&h[j0 + jj][cb + 4];
#pragma unroll
            for (int i = 0; i < 4; i++) {
                u64 a = dup2(((const float*)&av[i])[jj]);
                fma2(acc2[i][0], a, h0.x);
                fma2(acc2[i][1], a, h0.y);
                fma2(acc2[i][2], a, h1.x);
                fma2(acc2[i][3], a, h1.y);
            }
        }
    }
    // loads above are program-order before the stores below -> warp-safe in-place
    ulonglong2 b01 = *(const ulonglong2*)&bias[cb];
    ulonglong2 b23 = *(const ulonglong2*)&bias[cb + 4];
#pragma unroll
    for (int i = 0; i < 4; i++) {
        int row = 4 * ng + i;
        u64 o0 = acc2[i][0], o1 = acc2[i][1], o2 = acc2[i][2], o3 = acc2[i][3];
        add2(o0, b01.x); add2(o1, b01.y); add2(o2, b23.x); add2(o3, b23.y);
        ulonglong2 s0; s0.x = o0; s0.y = o1;
        ulonglong2 s1; s1.x = o2; s1.y = o3;
        *(ulonglong2*)&h[row][cb]     = s0;
        *(ulonglong2*)&h[row][cb + 4] = s1;
    }
    __syncthreads();   // next stage reads all channels
}

__global__ void __launch_bounds__(THREADS, 6) gat_fused_kernel(
    const float* __restrict__ xs,
    const float* __restrict__ pe,
    const float* __restrict__ W1,
    const float* __restrict__ as1, const float* __restrict__ ad1,
    const float* __restrict__ b1,
    const float* __restrict__ W2,
    const float* __restrict__ as2, const float* __restrict__ ad2,
    const float* __restrict__ b2,
    const float* __restrict__ b3,
    const float* __restrict__ lw,
    const float* __restrict__ lb,
    float* __restrict__ out,
    int R)
{
    __shared__ float hs[NCOL][FHP];
    __shared__ float alphas[HEADS][NCOL][NCOL];
    __shared__ float s_src[HEADS * NCOL];
    __shared__ float s_dst[HEADS * NCOL];
    __shared__ float xin[NCOL][XINP];
    __shared__ float ys[F3];

    const int g = blockIdx.x;
    const int b = g / R;
    const int r = g - b * R;
    const int t = threadIdx.x;
    const int lane = t & 31;
    const int w = t >> 5;
    const int cq = lane & 7;
    const int ngrp = lane >> 3;

    // ---- build input features ----
    for (int idx = t; idx < NCOL * 16; idx += THREADS) {
        int n = idx >> 4, f = idx & 15;
        float v;
        if (f == 0) v = xs[(size_t)(b * R + r) * NCOL + n];
        else        v = pe[(b * NCOL + n) * 15 + (f - 1)];
        xin[n][f] = v;
    }
    __syncthreads();

    // ---- layer 1 GEMM + score fold ----
    {
        const int cwb = 32 * w;
        u64 acc2[8][2];
#pragma unroll
        for (int nn = 0; nn < 8; nn++) { acc2[nn][0] = 0; acc2[nn][1] = 0; }
#pragma unroll
        for (int f0 = 0; f0 < 16; f0 += 4) {
            ulonglong2 wv[4];
#pragma unroll
            for (int k = 0; k < 4; k++)
                wv[k] = *(const ulonglong2*)(W1 + (f0 + k) * FH + cwb + 4 * cq);
#pragma unroll
            for (int nn = 0; nn < 8; nn++) {
                float4 hv = *(const float4*)&xin[4 * nn + ngrp][f0];
                u64 d0 = dup2(hv.x), d1 = dup2(hv.y), d2 = dup2(hv.z), d3 = dup2(hv.w);
                fma2(acc2[nn][0], d0, wv[0].x); fma2(acc2[nn][1], d0, wv[0].y);
                fma2(acc2[nn][0], d1, wv[1].x); fma2(acc2[nn][1], d1, wv[1].y);
                fma2(acc2[nn][0], d2, wv[2].x); fma2(acc2[nn][1], d2, wv[2].y);
                fma2(acc2[nn][0], d3, wv[3].x); fma2(acc2[nn][1], d3, wv[3].y);
            }
        }
        // score fold: warp w's channels are exactly head w's block
        {
            ulonglong2 av = *(const ulonglong2*)(as1 + cwb + 4 * cq);
            ulonglong2 dv = *(const ulonglong2*)(ad1 + cwb + 4 * cq);
#pragma unroll
            for (int nn = 0; nn < 8; nn++) {
                u64 ts = 0, td = 0;
                fma2(ts, acc2[nn][0], av.x); fma2(ts, acc2[nn][1], av.y);
                fma2(td, acc2[nn][0], dv.x); fma2(td, acc2[nn][1], dv.y);
                float2 ps = unpack2(ts), pd = unpack2(td);
                float ss = ps.x + ps.y, sd = pd.x + pd.y;
                ss += __shfl_xor_sync(0xffffffffu, ss, 1);
                sd += __shfl_xor_sync(0xffffffffu, sd, 1);
                ss += __shfl_xor_sync(0xffffffffu, ss, 2);
                sd += __shfl_xor_sync(0xffffffffu, sd, 2);
                ss += __shfl_xor_sync(0xffffffffu, ss, 4);
                sd += __shfl_xor_sync(0xffffffffu, sd, 4);
                if (cq == nn) {
                    s_src[w * 32 + 4 * nn + ngrp] = ss;
                    s_dst[w * 32 + 4 * nn + ngrp] = sd;
                }
            }
        }
#pragma unroll
        for (int nn = 0; nn < 8; nn++) {
            ulonglong2 o; o.x = acc2[nn][0]; o.y = acc2[nn][1];
            *(ulonglong2*)&hs[4 * nn + ngrp][cwb + 4 * cq] = o;
        }
    }
    gat_attention32_post(hs, b1, s_src, s_dst, alphas[w], w, lane);

    // ---- layer 2 GEMM + score fold ----
    {
        const int cwb = 32 * w;
        u64 acc2[8][2];
#pragma unroll
        for (int nn = 0; nn < 8; nn++) { acc2[nn][0] = 0; acc2[nn][1] = 0; }

#pragma unroll 2
        for (int f0 = 0; f0 < FH; f0 += 4) {
            ulonglong2 wv[4];
#pragma unroll
            for (int k = 0; k < 4; k++)
                wv[k] = *(const ulonglong2*)(W2 + (f0 + k) * FH + cwb + 4 * cq);
#pragma unroll
            for (int nn = 0; nn < 8; nn++) {
                float4 hv = *(const float4*)&hs[4 * nn + ngrp][f0];
                u64 d0 = dup2(hv.x), d1 = dup2(hv.y), d2 = dup2(hv.z), d3 = dup2(hv.w);
                fma2(acc2[nn][0], d0, wv[0].x); fma2(acc2[nn][1], d0, wv[0].y);
                fma2(acc2[nn][0], d1, wv[1].x); fma2(acc2[nn][1], d1, wv[1].y);
                fma2(acc2[nn][0], d2, wv[2].x); fma2(acc2[nn][1], d2, wv[2].y);
                fma2(acc2[nn][0], d3, wv[3].x); fma2(acc2[nn][1], d3, wv[3].y);
            }
        }
        // score fold for layer 2
        {
            ulonglong2 av = *(const ulonglong2*)(as2 + cwb + 4 * cq);
            ulonglong2 dv = *(const ulonglong2*)(ad2 + cwb + 4 * cq);
#pragma unroll
            for (int nn = 0; nn < 8; nn++) {
                u64 ts = 0, td = 0;
                fma2(ts, acc2[nn][0], av.x); fma2(ts, acc2[nn][1], av.y);
                fma2(td, acc2[nn][0], dv.x); fma2(td, acc2[nn][1], dv.y);
                float2 ps = unpack2(ts), pd = unpack2(td);
                float ss = ps.x + ps.y, sd = pd.x + pd.y;
                ss += __shfl_xor_sync(0xffffffffu, ss, 1);
                sd += __shfl_xor_sync(0xffffffffu, sd, 1);
                ss += __shfl_xor_sync(0xffffffffu, ss, 2);
                sd += __shfl_xor_sync(0xffffffffu, sd, 2);
                ss += __shfl_xor_sync(0xffffffffu, ss, 4);
                sd += __shfl_xor_sync(0xffffffffu, sd, 4);
                if (cq == nn) {
                    s_src[w * 32 + 4 * nn + ngrp] = ss;
                    s_dst[w * 32 + 4 * nn + ngrp] = sd;
                }
            }
        }
        __syncthreads();   // all warps done reading hs before overwrite
#pragma unroll
        for (int nn = 0; nn < 8; nn++) {
            ulonglong2 o; o.x = acc2[nn][0]; o.y = acc2[nn][1];
            *(ulonglong2*)&hs[4 * nn + ngrp][cwb + 4 * cq] = o;
        }
    }
    gat_attention32_post(hs, b2, s_src, s_dst, alphas[w], w, lane);

    // ---- layer 3 GEMM (warp w -> nodes 8w..8w+7, 32 padded channels) + score fold ----
    {
        u64 acc2[2][2];
        acc2[0][0] = acc2[0][1] = acc2[1][0] = acc2[1][1] = 0;

#pragma unroll 4
        for (int f0 = 0; f0 < FH; f0 += 4) {
            ulonglong2 wv[4];
#pragma unroll
            for (int k = 0; k < 4; k++)
                wv[k] = *(const ulonglong2*)(W3p_g + (f0 + k) * 32 + 4 * cq);
#pragma unroll
            for (int s = 0; s < 2; s++) {
                float4 hv = *(const float4*)&hs[8 * w + 4 * s + ngrp][f0];
                u64 d0 = dup2(hv.x), d1 = dup2(hv.y), d2 = dup2(hv.z), d3 = dup2(hv.w);
                fma2(acc2[s][0], d0, wv[0].x); fma2(acc2[s][1], d0, wv[0].y);
                fma2(acc2[s][0], d1, wv[1].x); fma2(acc2[s][1], d1, wv[1].y);
                fma2(acc2[s][0], d2, wv[2].x); fma2(acc2[s][1], d2, wv[2].y);
                fma2(acc2[s][0], d3, wv[3].x); fma2(acc2[s][1], d3, wv[3].y);
            }
        }
        // score fold: lane covers padded channels 4cq..4cq+3 of head cq>>1
        {
            ulonglong2 av = *(const ulonglong2*)(as3p_g + 4 * cq);
            ulonglong2 dv = *(const ulonglong2*)(ad3p_g + 4 * cq);
            float ssr[2], sdr[2];
#pragma unroll
            for (int s = 0; s < 2; s++) {
                u64 ts = 0, td = 0;
                fma2(ts, acc2[s][0], av.x); fma2(ts, acc2[s][1], av.y);
                fma2(td, acc2[s][0], dv.x); fma2(td, acc2[s][1], dv.y);
                float2 ps = unpack2(ts), pd = unpack2(td);
                ssr[s] = ps.x + ps.y; sdr[s] = pd.x + pd.y;
                ssr[s] += __shfl_xor_sync(0xffffffffu, ssr[s], 1);
                sdr[s] += __shfl_xor_sync(0xffffffffu, sdr[s], 1);
            }
            int h3 = cq >> 1;
#pragma unroll
            for (int s = 0; s < 2; s++) {
                int node = 8 * w + 4 * s + ngrp;
                if ((cq & 1) == 0) s_src[h3 * 32 + node] = ssr[s];
                else               s_dst[h3 * 32 + node] = sdr[s];
            }
        }
#pragma unroll
        for (int s = 0; s < 2; s++) {
            ulonglong2 o; o.x = acc2[s][0]; o.y = acc2[s][1];
            *(ulonglong2*)&hs[8 * w + 4 * s + ngrp][4 * cq] = o;
        }
    }
    __syncthreads();   // scores + h3 cross-warp

    // ---- layer 3 attention, beta-collapsed: y = sum_j beta[j] h3[j] + b3 ----
    {
        // softmax for target n = lane, head w
        const float sdst = s_dst[w * 32 + lane];
        float e[NCOL];
        float m = -1e30f;
#pragma unroll
        for (int q = 0; q < 8; q++) {
            float4 sv = *(const float4*)&s_src[w * 32 + 4 * q];
            e[4*q+0] = lrelu(sdst + sv.x);
            e[4*q+1] = lrelu(sdst + sv.y);
            e[4*q+2] = lrelu(sdst + sv.z);
            e[4*q+3] = lrelu(sdst + sv.w);
        }
#pragma unroll
        for (int j = 0; j < NCOL; j++) m = fmaxf(m, e[j]);
        float sum = 0.f;
#pragma unroll
        for (int j = 0; j < NCOL; j++) {
            e[j] = __expf(e[j] - m);
            sum += e[j];
        }
        const float rinv = 1.f / sum;
        const int rot = lane >> 2;
#pragma unroll
        for (int q = 0; q < 8; q++) {
            int col = ((q + rot) & 7) * 4;
            float4 v;
            v.x = e[4*q+0] * rinv;
            v.y = e[4*q+1] * rinv;
            v.z = e[4*q+2] * rinv;
            v.w = e[4*q+3] * rinv;
            *(float4*)&alphas[w][lane][col] = v;
        }
        __syncwarp();

        // beta[j] = mean_n alpha[n][j]  (rotated transpose read, lane = j)
        float beta = 0.f;
        const int jq = lane >> 2, jr = lane & 3;
#pragma unroll 8
        for (int n = 0; n < NCOL; n++)
            beta += alphas[w][n][(((jq + (n >> 2)) & 7) << 2) + jr];
        beta *= (1.f / 32.f);

        // y_head = sum_j beta[j] * h3[j][head cols], butterfly-reduced
        float4 hv0 = *(const float4*)&hs[lane][8 * w];
        float2 hv1 = *(const float2*)&hs[lane][8 * w + 4];
        u64 p0 = pack2(beta * hv0.x, beta * hv0.y);
        u64 p1 = pack2(beta * hv0.z, beta * hv0.w);
        u64 p2 = pack2(beta * hv1.x, beta * hv1.y);
#pragma unroll
        for (int off = 16; off >= 1; off >>= 1) {
            add2(p0, shfl_xor_u64(p0, off));
            add2(p1, shfl_xor_u64(p1, off));
            add2(p2, shfl_xor_u64(p2, off));
        }
        if (lane == 0) {
            float2 a = unpack2(p0), bb = unpack2(p1), c = unpack2(p2);
            ys[w * 6 + 0] = a.x  + b3[w * 6 + 0];
            ys[w * 6 + 1] = a.y  + b3[w * 6 + 1];
            ys[w * 6 + 2] = bb.x + b3[w * 6 + 2];
            ys[w * 6 + 3] = bb.y + b3[w * 6 + 3];
            ys[w * 6 + 4] = c.x  + b3[w * 6 + 4];
            ys[w * 6 + 5] = c.y  + b3[w * 6 + 5];
        }
    }
    __syncthreads();

    // ---- final linear on the mean vector ----
    if (t < 64) {
        float acc = lb[t];
#pragma unroll
        for (int k = 0; k < F3; k++) acc = fmaf(ys[k], lw[k * 64 + t], acc);
        out[(size_t)g * 64 + t] = acc;
    }
}

extern "C" void kernel_launch(void* const* d_in, const int* in_sizes, int n_in,
                              void* d_out, int out_size)
{
    const float* xs  = (const float*)d_in[0];
    const float* pe  = (const float*)d_in[1];
    const float* W1  = (const float*)d_in[2];
    const float* as1 = (const float*)d_in[3];
    const float* ad1 = (const float*)d_in[4];
    const float* b1  = (const float*)d_in[5];
    const float* W2  = (const float*)d_in[6];
    const float* as2 = (const float*)d_in[7];
    const float* ad2 = (const float*)d_in[8];
    const float* b2  = (const float*)d_in[9];
    const float* W3  = (const float*)d_in[10];
    const float* as3 = (const float*)d_in[11];
    const float* ad3 = (const float*)d_in[12];
    const float* b3  = (const float*)d_in[13];
    const float* lw  = (const float*)d_in[14];
    const float* lb  = (const float*)d_in[15];
    float* out = (float*)d_out;

    int B = in_sizes[1] / (32 * 15);
    int R = in_sizes[0] / (B * 32);
    int G = B * R;

    prep_kernel<<<33, 128>>>(W3, as3, ad3);
    gat_fused_kernel<<<G, THREADS>>>(xs, pe, W1, as1, ad1, b1,
                                     W2, as2, ad2, b2,
                                     b3, lw, lb, out, R);
}